// round 2
// baseline (speedup 1.0000x reference)
#include <cuda_runtime.h>

// BiasedFeatureDropout: out = x * 1.25 * (threefry_bits(i) < T(channel))
// Bit-exact JAX partitionable threefry-2x32, keys (0,1), counter hi=0.
//
// Pipe-balancing build: threefry adds are forced onto the fma pipe via
// mad.lo.u32 with a runtime 'one' operand (IMAD, fma pipe); 6 of the 19
// post-fold rounds use a mul.wide.u32 rotate (fma) + single LOP3 (a|b)^c
// (alu) so alu/fma land at ~37/36 warp-instr per element each.

static constexpr unsigned KS2      = 0x1BD11BDBu;   // 0 ^ 1 ^ 0x1BD11BDA
static constexpr unsigned HW       = 56u * 56u;     // 3136, divisible by 8
static constexpr unsigned THR_BIAS = 858993664u;    // keep=0.2f
static constexpr unsigned THR_REG  = 3435974144u;   // keep=0.8f

// a*one + b  -> IMAD (fma pipe); 'one' is a runtime kernel arg (==1)
__device__ __forceinline__ unsigned madd(unsigned a, unsigned one, unsigned b) {
    unsigned r;
    asm("mad.lo.u32 %0, %1, %2, %3;" : "=r"(r) : "r"(a), "r"(one), "r"(b));
    return r;
}

// rotl(x, r) ^ c  via  {hi:lo} = (u64)x * (1u<<r); (lo|hi)^c in one LOP3.
// p2 must equal (1u << r) at runtime (opaque to the compiler).
__device__ __forceinline__ unsigned rotB(unsigned x, unsigned p2, unsigned c) {
    unsigned r, lo, hi;
    asm("{\n\t"
        ".reg .b64 t;\n\t"
        "mul.wide.u32 t, %3, %4;\n\t"
        "mov.b64 {%1, %2}, t;\n\t"
        "lop3.b32 %0, %1, %2, %5, 0x56;\n\t"   // (lo | hi) ^ c
        "}"
        : "=r"(r), "=r"(lo), "=r"(hi)
        : "r"(x), "r"(p2), "r"(c));
    return r;
}

// classic round: SHF rotate (alu) + LOP3 xor (alu) + IMAD add (fma)
#define TF_A(rr) { x0 = madd(x1, one, x0); x1 = __funnelshift_l(x1, x1, (rr)) ^ x0; }
// wide-mul round: IMAD add + IMAD.WIDE rotate (fma) + LOP3 (alu)
#define TF_B(pp) { x0 = madd(x1, one, x0); x1 = rotB(x1, (pp), x0); }

__device__ __forceinline__ unsigned threefry_bits(
    unsigned ctr, unsigned one,
    unsigned p17, unsigned p16, unsigned p26, unsigned p29, unsigned p24)
{
    unsigned x0, x1;
    x1 = madd(ctr, one, 1u);                 // x1 = ctr + ks1(=1)
    // --- group 0 (13,15,26,6); x0 starts at 0+ks0(=0) so round 1 folds ---
    x0 = x1;                                 // x0 = 0 + x1
    x1 = __funnelshift_l(x1, x1, 13) ^ x0;
    TF_A(15) TF_A(26) TF_A(6)
    x0 = madd(x0, one, 1u);  x1 = madd(x1, one, KS2 + 1u);
    // --- group 1 (17,29,16,24) ---
    TF_B(p17) TF_A(29) TF_B(p16) TF_A(24)
    x0 = madd(x0, one, KS2); x1 = madd(x1, one, 2u);
    // --- group 2 (13,15,26,6) ---
    TF_A(13) TF_A(15) TF_B(p26) TF_A(6)
    /* x0 += ks0(=0) */      x1 = madd(x1, one, 1u + 3u);
    // --- group 3 (17,29,16,24) ---
    TF_A(17) TF_B(p29) TF_A(16) TF_B(p24)
    x0 = madd(x0, one, 1u);  x1 = madd(x1, one, KS2 + 4u);
    // --- group 4 (13,15,26,6) ---
    TF_A(13) TF_A(15) TF_B(p26) TF_A(6)
    x0 = madd(x0, one, KS2); x1 = madd(x1, one, 5u);
    return x0 ^ x1;
}

__global__ __launch_bounds__(256)
void biased_dropout_kernel(const float4* __restrict__ x,
                           float4* __restrict__ y,
                           unsigned one,            // always 1, opaque to ptxas
                           unsigned n_thr) {
    unsigned t = blockIdx.x * blockDim.x + threadIdx.x;
    if (t >= n_thr) return;

    unsigned base = t * 8u;
    // channel = (elem / HW) % 256; HW % 8 == 0 so all 8 elems share it
    unsigned ch  = (base / HW) & 255u;
    unsigned thr = (ch < 32u) ? THR_BIAS : THR_REG;

    // rotation pow2s (uniform, hoisted; opaque because 'one' is runtime)
    unsigned p17 = one << 17, p16 = one << 16, p26 = one << 26,
             p29 = one << 29, p24 = one << 24;

    float4 v0 = x[2u * t];
    float4 v1 = x[2u * t + 1u];

    unsigned b[8];
#pragma unroll
    for (int i = 0; i < 8; i++)
        b[i] = threefry_bits(base + (unsigned)i, one, p17, p16, p26, p29, p24);

    float4 o0, o1;
    o0.x = (b[0] < thr) ? v0.x * 1.25f : 0.0f;
    o0.y = (b[1] < thr) ? v0.y * 1.25f : 0.0f;
    o0.z = (b[2] < thr) ? v0.z * 1.25f : 0.0f;
    o0.w = (b[3] < thr) ? v0.w * 1.25f : 0.0f;
    o1.x = (b[4] < thr) ? v1.x * 1.25f : 0.0f;
    o1.y = (b[5] < thr) ? v1.y * 1.25f : 0.0f;
    o1.z = (b[6] < thr) ? v1.z * 1.25f : 0.0f;
    o1.w = (b[7] < thr) ? v1.w * 1.25f : 0.0f;

    y[2u * t]      = o0;
    y[2u * t + 1u] = o1;
}

extern "C" void kernel_launch(void* const* d_in, const int* in_sizes, int n_in,
                              void* d_out, int out_size) {
    (void)n_in; (void)out_size;
    const float4* x = (const float4*)d_in[0];
    float4* y = (float4*)d_out;
    unsigned n = (unsigned)in_sizes[0];          // 51,380,224
    unsigned n_thr = n / 8u;                     // 6,422,528 (exact)
    unsigned blocks = (n_thr + 255u) / 256u;     // 25,088
    biased_dropout_kernel<<<blocks, 256>>>(x, y, 1u, n_thr);
}